// round 7
// baseline (speedup 1.0000x reference)
#include <cuda_runtime.h>
#include <cuda_bf16.h>
#include <cstdint>

#define NN 100000
#define EE 600000
#define SCAN_NB 98   // 98 * 1024 >= 100000

// ---------------- scratch (device globals; no allocs allowed) ----------------
__device__ float g_h [(size_t)NN * 128];
__device__ float g_x1[(size_t)NN * 128];
__device__ float g_x2[(size_t)NN * 128];
__device__ float g_dinv[NN];
__device__ int   g_deg[NN];
__device__ int   g_cur[NN];
__device__ int   g_rs[NN + 1];
__device__ int   g_csrc[EE];
__device__ int   g_bsum[SCAN_NB];
__device__ int   g_boff[SCAN_NB];
// pre-split W, transposed: Bt[n][k] = W[k][n], bf16 hi/lo, 3 layers
__device__ __align__(16) __nv_bfloat16 g_Bhi[3 * 128 * 128];
__device__ __align__(16) __nv_bfloat16 g_Blo[3 * 128 * 128];

// ---------------- PTX helpers (plain sm_103-safe: ldmatrix + mma.sync) -------
__device__ __forceinline__ uint32_t smem_u32(const void* p) {
    uint32_t a;
    asm("{ .reg .u64 t; cvta.to.shared.u64 t, %1; cvt.u32.u64 %0, t; }" : "=r"(a) : "l"(p));
    return a;
}
#define LDSM_X4(r0, r1, r2, r3, addr) \
    asm volatile("ldmatrix.sync.aligned.m8n8.x4.shared.b16 {%0,%1,%2,%3}, [%4];" \
                 : "=r"(r0), "=r"(r1), "=r"(r2), "=r"(r3) : "r"(addr))
#define MMA_BF16(c, a, b) \
    asm volatile("mma.sync.aligned.m16n8k16.row.col.f32.bf16.bf16.f32 " \
                 "{%0,%1,%2,%3}, {%4,%5,%6,%7}, {%8,%9}, {%0,%1,%2,%3};" \
                 : "+f"((c)[0]), "+f"((c)[1]), "+f"((c)[2]), "+f"((c)[3]) \
                 : "r"((a)[0]), "r"((a)[1]), "r"((a)[2]), "r"((a)[3]), \
                   "r"((b)[0]), "r"((b)[1]))

// ---------------- graph preprocessing ----------------
__global__ void init_kernel() {
    int i = blockIdx.x * blockDim.x + threadIdx.x;
    if (i < NN) { g_deg[i] = 0; g_cur[i] = 0; }
}
__global__ void count_kernel(const int* __restrict__ dst) {
    int e = blockIdx.x * blockDim.x + threadIdx.x;
    if (e < EE) atomicAdd(&g_deg[dst[e]], 1);
}
__global__ void dinv_kernel() {
    int i = blockIdx.x * blockDim.x + threadIdx.x;
    if (i < NN) g_dinv[i] = rsqrtf((float)(g_deg[i] + 1));
}
__global__ void scan1_kernel() {
    __shared__ int ws[32];
    int tid = threadIdx.x, lane = tid & 31, w = tid >> 5;
    int i = blockIdx.x * 1024 + tid;
    int v = (i < NN) ? g_deg[i] : 0;
    int x = v;
    #pragma unroll
    for (int o = 1; o < 32; o <<= 1) {
        int y = __shfl_up_sync(0xffffffffu, x, o);
        if (lane >= o) x += y;
    }
    if (lane == 31) ws[w] = x;
    __syncthreads();
    if (w == 0) {
        int s = ws[lane];
        #pragma unroll
        for (int o = 1; o < 32; o <<= 1) {
            int y = __shfl_up_sync(0xffffffffu, s, o);
            if (lane >= o) s += y;
        }
        ws[lane] = s;
    }
    __syncthreads();
    int off = (w == 0) ? 0 : ws[w - 1];
    if (i < NN) g_rs[i] = off + x - v;
    if (tid == 0) g_bsum[blockIdx.x] = ws[31];
}
__global__ void scan2_kernel() {
    if (threadIdx.x == 0) {
        int run = 0;
        for (int i = 0; i < SCAN_NB; i++) { int t = g_bsum[i]; g_boff[i] = run; run += t; }
        g_rs[NN] = run;
    }
}
__global__ void scan3_kernel() {
    int i = blockIdx.x * 1024 + threadIdx.x;
    if (i < NN) g_rs[i] += g_boff[blockIdx.x];
}
__global__ void fill_kernel(const int* __restrict__ src, const int* __restrict__ dst) {
    int e = blockIdx.x * blockDim.x + threadIdx.x;
    if (e < EE) {
        int d = dst[e];
        int p = atomicAdd(&g_cur[d], 1);
        g_csrc[g_rs[d] + p] = src[e];
    }
}

// ---------------- W prep: Bt[n][k] = W[k][n], split fp32 -> bf16 hi/lo -------
__global__ void prep_w_kernel(const float* __restrict__ Ws) {
    int idx = blockIdx.x * blockDim.x + threadIdx.x;
    if (idx >= 3 * 16384) return;
    int l = idx >> 14, rem = idx & 16383;
    int n = rem >> 7, k = rem & 127;
    float v = Ws[l * 16384 + k * 128 + n];
    __nv_bfloat16 hi = __float2bfloat16(v);
    __nv_bfloat16 lo = __float2bfloat16(v - __bfloat162float(hi));
    g_Bhi[l * 16384 + n * 128 + k] = hi;
    g_Blo[l * 16384 + n * 128 + k] = lo;
}

// ---------------- tensor-core GEMM via mma.sync (bf16 2-term split) ----------
// h[N,128] = x[N,128] @ W[128,128]; D = xh*wh + xh*wl + xl*wh, fp32 accum.
// CTA: 64 rows x 128 cols, 256 threads (8 warps), warp tile 32x32.
// 2 CTAs/SM (104 KB smem). smem stride 136 bf16 -> conflict-free ldmatrix.
#define XS 136
#define XT_B (64  * XS * 2)   // 17408 per X tile
#define WT_B (128 * XS * 2)   // 34816 per W tile
#define SM_TOTAL_G (2 * XT_B + 2 * WT_B)   // 104448
#define CS 132                 // C epilogue stride (floats)

__global__ __launch_bounds__(256, 2) void gemm_tc_kernel(const float* __restrict__ x,
                                                         int layer,
                                                         float* __restrict__ h) {
    extern __shared__ __align__(16) char smem[];
    char* sXh = smem;
    char* sXl = smem + XT_B;
    char* sWh = smem + 2 * XT_B;
    char* sWl = smem + 2 * XT_B + WT_B;

    int tid = threadIdx.x, lane = tid & 31, wid = tid >> 5;
    int row0 = blockIdx.x * 64;

    // ---- stage W tiles (pre-split bf16, L2-resident) ----
    {
        const uint4* bh = (const uint4*)(g_Bhi + layer * 16384);
        const uint4* bl = (const uint4*)(g_Blo + layer * 16384);
        #pragma unroll
        for (int i = 0; i < 8; i++) {
            int idx = tid + i * 256;            // 2048 uint4 = 128 n x 16 kq
            int n = idx >> 4, kq = idx & 15;
            uint32_t off = (uint32_t)(n * XS + kq * 8) * 2;
            *(uint4*)(sWh + off) = bh[idx];
            *(uint4*)(sWl + off) = bl[idx];
        }
    }
    // ---- stage X: fp32 -> bf16 hi/lo (64 rows) ----
    {
        #pragma unroll
        for (int i = 0; i < 8; i++) {
            int idx = tid + i * 256;            // 2048 float4 = 64 r x 32 c4
            int r = idx >> 5, c4 = idx & 31;
            int gr = row0 + r;
            float4 v = make_float4(0.f, 0.f, 0.f, 0.f);
            if (gr < NN) v = *(const float4*)&x[(size_t)gr * 128 + c4 * 4];
            __nv_bfloat16 h0 = __float2bfloat16(v.x), h1 = __float2bfloat16(v.y);
            __nv_bfloat16 h2 = __float2bfloat16(v.z), h3 = __float2bfloat16(v.w);
            __nv_bfloat16 l0 = __float2bfloat16(v.x - __bfloat162float(h0));
            __nv_bfloat16 l1 = __float2bfloat16(v.y - __bfloat162float(h1));
            __nv_bfloat16 l2 = __float2bfloat16(v.z - __bfloat162float(h2));
            __nv_bfloat16 l3 = __float2bfloat16(v.w - __bfloat162float(h3));
            uint2 hp, lp;
            hp.x = (uint32_t)__bfloat16_as_ushort(h0) | ((uint32_t)__bfloat16_as_ushort(h1) << 16);
            hp.y = (uint32_t)__bfloat16_as_ushort(h2) | ((uint32_t)__bfloat16_as_ushort(h3) << 16);
            lp.x = (uint32_t)__bfloat16_as_ushort(l0) | ((uint32_t)__bfloat16_as_ushort(l1) << 16);
            lp.y = (uint32_t)__bfloat16_as_ushort(l2) | ((uint32_t)__bfloat16_as_ushort(l3) << 16);
            uint32_t off = (uint32_t)(r * XS + c4 * 4) * 2;
            *(uint2*)(sXh + off) = hp;
            *(uint2*)(sXl + off) = lp;
        }
    }
    __syncthreads();

    // ---- compute: warp grid 2x4, warp tile 32 rows x 32 cols ----
    int mrow = (wid >> 2) * 32;     // 0 / 32
    int ncol = (wid & 3) * 32;      // 0 / 32 / 64 / 96

    float c[2][4][4];
    #pragma unroll
    for (int mt = 0; mt < 2; mt++)
        #pragma unroll
        for (int nt = 0; nt < 4; nt++)
            #pragma unroll
            for (int j = 0; j < 4; j++) c[mt][nt][j] = 0.f;

    uint32_t sXh_b = smem_u32(sXh), sXl_b = smem_u32(sXl);
    uint32_t sWh_b = smem_u32(sWh), sWl_b = smem_u32(sWl);

    // A ldmatrix.x4 lane addressing (validated R6): rows lane&15, k-half lane>>4
    int a_row = lane & 15, a_kq = lane >> 4;
    // B ldmatrix.x4 over an n-pair: n-octet (lane>>4)&1, row lane&7, k-half (lane>>3)&1
    int b_nrow = ((lane >> 4) & 1) * 8 + (lane & 7);
    int b_kq   = (lane >> 3) & 1;

    #pragma unroll
    for (int ks = 0; ks < 8; ks++) {
        uint32_t ah[2][4], al[2][4];
        #pragma unroll
        for (int mt = 0; mt < 2; mt++) {
            uint32_t aoff = (uint32_t)((mrow + mt * 16 + a_row) * XS + ks * 16 + a_kq * 8) * 2;
            LDSM_X4(ah[mt][0], ah[mt][1], ah[mt][2], ah[mt][3], sXh_b + aoff);
            LDSM_X4(al[mt][0], al[mt][1], al[mt][2], al[mt][3], sXl_b + aoff);
        }
        uint32_t bh[4][2], bl[4][2];
        #pragma unroll
        for (int np = 0; np < 2; np++) {
            uint32_t boff = (uint32_t)((ncol + np * 16 + b_nrow) * XS + ks * 16 + b_kq * 8) * 2;
            LDSM_X4(bh[np*2][0], bh[np*2][1], bh[np*2+1][0], bh[np*2+1][1], sWh_b + boff);
            LDSM_X4(bl[np*2][0], bl[np*2][1], bl[np*2+1][0], bl[np*2+1][1], sWl_b + boff);
        }
        #pragma unroll
        for (int nt = 0; nt < 4; nt++) {
            #pragma unroll
            for (int mt = 0; mt < 2; mt++) {
                MMA_BF16(c[mt][nt], ah[mt], bh[nt]);
                MMA_BF16(c[mt][nt], ah[mt], bl[nt]);
                MMA_BF16(c[mt][nt], al[mt], bh[nt]);
            }
        }
    }

    // ---- epilogue: fragments -> smem (reuse X tiles) -> coalesced global ----
    __syncthreads();                       // all LDSM reads of sX done
    float* sC = (float*)smem;              // 64 x CS floats = 33792 B <= 2*XT_B
    int qrow = lane >> 2;                  // 0..7
    int qcol = (lane & 3) * 2;             // 0,2,4,6
    #pragma unroll
    for (int mt = 0; mt < 2; mt++) {
        int r = mrow + mt * 16 + qrow;
        #pragma unroll
        for (int nt = 0; nt < 4; nt++) {
            int n = ncol + nt * 8 + qcol;
            *(float2*)&sC[r * CS + n]       = make_float2(c[mt][nt][0], c[mt][nt][1]);
            *(float2*)&sC[(r + 8) * CS + n] = make_float2(c[mt][nt][2], c[mt][nt][3]);
        }
    }
    __syncthreads();
    #pragma unroll
    for (int i = 0; i < 8; i++) {
        int idx = tid + i * 256;           // 2048 float4 = 64 r x 32 c4
        int r = idx >> 5, c4 = idx & 31;
        int gr = row0 + r;
        if (gr < NN) {
            float4 v = *(float4*)&sC[r * CS + c4 * 4];
            *(float4*)&h[(size_t)gr * 128 + c4 * 4] = v;
        }
    }
}

// ---------------- aggregation (atomic-free CSR gather) ----------------
__global__ __launch_bounds__(256) void agg_kernel(const float* __restrict__ h,
                                                  const float* __restrict__ bias,
                                                  float* __restrict__ out) {
    int n = (blockIdx.x * blockDim.x + threadIdx.x) >> 5;
    if (n >= NN) return;
    int lane = threadIdx.x & 31;
    int c0   = lane * 4;

    float dn = g_dinv[n];
    float4 hn = *(const float4*)&h[(size_t)n * 128 + c0];
    float sw = dn * dn;
    float4 a = make_float4(hn.x * sw, hn.y * sw, hn.z * sw, hn.w * sw);

    int e  = g_rs[n];
    int s1 = g_rs[n + 1];
    for (; e + 4 <= s1; e += 4) {
        int i0 = g_csrc[e], i1 = g_csrc[e + 1], i2 = g_csrc[e + 2], i3 = g_csrc[e + 3];
        float w0 = g_dinv[i0] * dn, w1 = g_dinv[i1] * dn;
        float w2 = g_dinv[i2] * dn, w3 = g_dinv[i3] * dn;
        float4 h0 = *(const float4*)&h[(size_t)i0 * 128 + c0];
        float4 h1 = *(const float4*)&h[(size_t)i1 * 128 + c0];
        float4 h2 = *(const float4*)&h[(size_t)i2 * 128 + c0];
        float4 h3 = *(const float4*)&h[(size_t)i3 * 128 + c0];
        a.x += h0.x * w0 + h1.x * w1 + h2.x * w2 + h3.x * w3;
        a.y += h0.y * w0 + h1.y * w1 + h2.y * w2 + h3.y * w3;
        a.z += h0.z * w0 + h1.z * w1 + h2.z * w2 + h3.z * w3;
        a.w += h0.w * w0 + h1.w * w1 + h2.w * w2 + h3.w * w3;
    }
    for (; e < s1; ++e) {
        int s = g_csrc[e];
        float w = g_dinv[s] * dn;
        float4 hv = *(const float4*)&h[(size_t)s * 128 + c0];
        a.x += hv.x * w; a.y += hv.y * w; a.z += hv.z * w; a.w += hv.w * w;
    }
    float4 bv = *(const float4*)&bias[c0];
    a.x = fmaxf(a.x + bv.x, 0.f);
    a.y = fmaxf(a.y + bv.y, 0.f);
    a.z = fmaxf(a.z + bv.z, 0.f);
    a.w = fmaxf(a.w + bv.w, 0.f);
    *(float4*)&out[(size_t)n * 128 + c0] = a;
}

// ---------------- launch ----------------
extern "C" void kernel_launch(void* const* d_in, const int* in_sizes, int n_in,
                              void* d_out, int out_size) {
    const int*   ei  = (const int*)d_in[0];      // [2, 600000]
    const float* emb = (const float*)d_in[1];    // [100000, 128]
    const float* Ws  = (const float*)d_in[2];    // [3, 128, 128]
    const float* bs  = (const float*)d_in[3];    // [3, 128]
    float* out = (float*)d_out;

    const int* src = ei;
    const int* dst = ei + EE;

    float *ph, *px1, *px2;
    cudaGetSymbolAddress((void**)&ph,  g_h);
    cudaGetSymbolAddress((void**)&px1, g_x1);
    cudaGetSymbolAddress((void**)&px2, g_x2);

    cudaFuncSetAttribute(gemm_tc_kernel, cudaFuncAttributeMaxDynamicSharedMemorySize, SM_TOTAL_G);

    const int TB = 256;
    int gN = (NN + TB - 1) / TB;
    int gE = (EE + TB - 1) / TB;
    int gG = (NN + 63) / 64;            // 1563 CTAs (64 rows each)
    int gA = (NN * 32 + TB - 1) / TB;   // one warp per node

    // one-time-per-launch prep
    prep_w_kernel<<<(3 * 16384 + 255) / 256, 256>>>(Ws);
    init_kernel  <<<gN, TB>>>();
    count_kernel <<<gE, TB>>>(dst);
    dinv_kernel  <<<gN, TB>>>();
    scan1_kernel <<<SCAN_NB, 1024>>>();
    scan2_kernel <<<1, 32>>>();
    scan3_kernel <<<SCAN_NB, 1024>>>();
    fill_kernel  <<<gE, TB>>>(src, dst);

    // layer 0
    gemm_tc_kernel<<<gG, 256, SM_TOTAL_G>>>(emb, 0, ph);
    agg_kernel    <<<gA, TB>>>(ph, bs,       px1);
    // layer 1
    gemm_tc_kernel<<<gG, 256, SM_TOTAL_G>>>(px1, 1, ph);
    agg_kernel    <<<gA, TB>>>(ph, bs + 128, px2);
    // layer 2
    gemm_tc_kernel<<<gG, 256, SM_TOTAL_G>>>(px2, 2, ph);
    agg_kernel    <<<gA, TB>>>(ph, bs + 256, out);
}

// round 9
// speedup vs baseline: 1.1309x; 1.1309x over previous
#include <cuda_runtime.h>
#include <cuda_bf16.h>
#include <cstdint>

#define NN 100000
#define EE 600000
#define SCAN_NB 98   // 98 * 1024 >= 100000

// ---------------- scratch (device globals; no allocs allowed) ----------------
__device__ float g_h [(size_t)NN * 128];
__device__ float g_x1[(size_t)NN * 128];
__device__ float g_x2[(size_t)NN * 128];
__device__ float g_dinv[NN];
__device__ int   g_deg[NN];
__device__ int   g_cur[NN];
__device__ int   g_rs[NN + 1];
__device__ int   g_csrc[EE];
__device__ int   g_bsum[SCAN_NB];
__device__ int   g_boff[SCAN_NB];
// pre-split W, transposed: Bt[n][k] = W[k][n], bf16 hi/lo, 3 layers
__device__ __align__(16) __nv_bfloat16 g_Bhi[3 * 128 * 128];
__device__ __align__(16) __nv_bfloat16 g_Blo[3 * 128 * 128];

// ---------------- PTX helpers (plain sm_103-safe: ldmatrix + mma.sync) -------
__device__ __forceinline__ uint32_t smem_u32(const void* p) {
    uint32_t a;
    asm("{ .reg .u64 t; cvta.to.shared.u64 t, %1; cvt.u32.u64 %0, t; }" : "=r"(a) : "l"(p));
    return a;
}
#define LDSM_X4(r0, r1, r2, r3, addr) \
    asm volatile("ldmatrix.sync.aligned.m8n8.x4.shared.b16 {%0,%1,%2,%3}, [%4];" \
                 : "=r"(r0), "=r"(r1), "=r"(r2), "=r"(r3) : "r"(addr))
#define MMA_BF16(c, a, b) \
    asm volatile("mma.sync.aligned.m16n8k16.row.col.f32.bf16.bf16.f32 " \
                 "{%0,%1,%2,%3}, {%4,%5,%6,%7}, {%8,%9}, {%0,%1,%2,%3};" \
                 : "+f"((c)[0]), "+f"((c)[1]), "+f"((c)[2]), "+f"((c)[3]) \
                 : "r"((a)[0]), "r"((a)[1]), "r"((a)[2]), "r"((a)[3]), \
                   "r"((b)[0]), "r"((b)[1]))

// ---------------- graph preprocessing ----------------
__global__ void init_kernel() {
    int i = blockIdx.x * blockDim.x + threadIdx.x;
    if (i < NN) { g_deg[i] = 0; g_cur[i] = 0; }
}
__global__ void count_kernel(const int* __restrict__ dst) {
    int e = blockIdx.x * blockDim.x + threadIdx.x;
    if (e < EE) atomicAdd(&g_deg[dst[e]], 1);
}
__global__ void dinv_kernel() {
    int i = blockIdx.x * blockDim.x + threadIdx.x;
    if (i < NN) g_dinv[i] = rsqrtf((float)(g_deg[i] + 1));
}
__global__ void scan1_kernel() {
    __shared__ int ws[32];
    int tid = threadIdx.x, lane = tid & 31, w = tid >> 5;
    int i = blockIdx.x * 1024 + tid;
    int v = (i < NN) ? g_deg[i] : 0;
    int x = v;
    #pragma unroll
    for (int o = 1; o < 32; o <<= 1) {
        int y = __shfl_up_sync(0xffffffffu, x, o);
        if (lane >= o) x += y;
    }
    if (lane == 31) ws[w] = x;
    __syncthreads();
    if (w == 0) {
        int s = ws[lane];
        #pragma unroll
        for (int o = 1; o < 32; o <<= 1) {
            int y = __shfl_up_sync(0xffffffffu, s, o);
            if (lane >= o) s += y;
        }
        ws[lane] = s;
    }
    __syncthreads();
    int off = (w == 0) ? 0 : ws[w - 1];
    if (i < NN) g_rs[i] = off + x - v;
    if (tid == 0) g_bsum[blockIdx.x] = ws[31];
}
__global__ void scan2_kernel() {
    if (threadIdx.x == 0) {
        int run = 0;
        for (int i = 0; i < SCAN_NB; i++) { int t = g_bsum[i]; g_boff[i] = run; run += t; }
        g_rs[NN] = run;
    }
}
__global__ void scan3_kernel() {
    int i = blockIdx.x * 1024 + threadIdx.x;
    if (i < NN) g_rs[i] += g_boff[blockIdx.x];
}
__global__ void fill_kernel(const int* __restrict__ src, const int* __restrict__ dst) {
    int e = blockIdx.x * blockDim.x + threadIdx.x;
    if (e < EE) {
        int d = dst[e];
        int p = atomicAdd(&g_cur[d], 1);
        g_csrc[g_rs[d] + p] = src[e];
    }
}

// ---------------- W prep: Bt[n][k] = W[k][n], split fp32 -> bf16 hi/lo -------
__global__ void prep_w_kernel(const float* __restrict__ Ws) {
    int idx = blockIdx.x * blockDim.x + threadIdx.x;
    if (idx >= 3 * 16384) return;
    int l = idx >> 14, rem = idx & 16383;
    int n = rem >> 7, k = rem & 127;
    float v = Ws[l * 16384 + k * 128 + n];
    __nv_bfloat16 hi = __float2bfloat16(v);
    __nv_bfloat16 lo = __float2bfloat16(v - __bfloat162float(hi));
    g_Bhi[l * 16384 + n * 128 + k] = hi;
    g_Blo[l * 16384 + n * 128 + k] = lo;
}

// ---------------- persistent tensor-core GEMM (bf16 2-term split) ------------
// h[N,128] = x[N,128] @ W[128,128]; D = xh*wh + xh*wl + xl*wh, fp32 accum.
// Grid = 296 persistent CTAs (2/SM); each stages W ONCE, loops over 64-row tiles.
#define XS 136
#define XT_B (64  * XS * 2)   // 17408 per X tile
#define WT_B (128 * XS * 2)   // 34816 per W tile
#define SM_TOTAL_G (2 * XT_B + 2 * WT_B)   // 104448
#define CS 132                 // C epilogue stride (floats)
#define GPER 296               // persistent grid (2 x 148 SMs)
#define NTILES ((NN + 63) / 64)

__global__ __launch_bounds__(256, 2) void gemm_tc_kernel(const float* __restrict__ x,
                                                         int layer,
                                                         float* __restrict__ h) {
    extern __shared__ __align__(16) char smem[];
    char* sXh = smem;
    char* sXl = smem + XT_B;
    char* sWh = smem + 2 * XT_B;
    char* sWl = smem + 2 * XT_B + WT_B;
    float* sC = (float*)smem;              // epilogue overlay on sXh/sXl

    int tid = threadIdx.x, lane = tid & 31, wid = tid >> 5;

    // ---- stage W tiles once (pre-split bf16, L2-resident) ----
    {
        const uint4* bh = (const uint4*)(g_Bhi + layer * 16384);
        const uint4* bl = (const uint4*)(g_Blo + layer * 16384);
        #pragma unroll
        for (int i = 0; i < 8; i++) {
            int idx = tid + i * 256;            // 2048 uint4 = 128 n x 16 kq
            int n = idx >> 4, kq = idx & 15;
            uint32_t off = (uint32_t)(n * XS + kq * 8) * 2;
            *(uint4*)(sWh + off) = bh[idx];
            *(uint4*)(sWl + off) = bl[idx];
        }
    }

    int mrow = (wid >> 2) * 32;     // 0 / 32
    int ncol = (wid & 3) * 32;      // 0 / 32 / 64 / 96
    uint32_t sXh_b = smem_u32(sXh), sXl_b = smem_u32(sXl);
    uint32_t sWh_b = smem_u32(sWh), sWl_b = smem_u32(sWl);
    int a_row = lane & 15, a_kq = lane >> 4;
    int b_nrow = ((lane >> 4) & 1) * 8 + (lane & 7);
    int b_kq   = (lane >> 3) & 1;
    int qrow = lane >> 2;
    int qcol = (lane & 3) * 2;

    for (int tile = blockIdx.x; tile < NTILES; tile += GPER) {
        int row0 = tile * 64;

        // ---- stage X: fp32 -> bf16 hi/lo (64 rows) ----
        #pragma unroll
        for (int i = 0; i < 8; i++) {
            int idx = tid + i * 256;            // 2048 float4 = 64 r x 32 c4
            int r = idx >> 5, c4 = idx & 31;
            int gr = row0 + r;
            float4 v = make_float4(0.f, 0.f, 0.f, 0.f);
            if (gr < NN) v = *(const float4*)&x[(size_t)gr * 128 + c4 * 4];
            __nv_bfloat16 h0 = __float2bfloat16(v.x), h1 = __float2bfloat16(v.y);
            __nv_bfloat16 h2 = __float2bfloat16(v.z), h3 = __float2bfloat16(v.w);
            __nv_bfloat16 l0 = __float2bfloat16(v.x - __bfloat162float(h0));
            __nv_bfloat16 l1 = __float2bfloat16(v.y - __bfloat162float(h1));
            __nv_bfloat16 l2 = __float2bfloat16(v.z - __bfloat162float(h2));
            __nv_bfloat16 l3 = __float2bfloat16(v.w - __bfloat162float(h3));
            uint2 hp, lp;
            hp.x = (uint32_t)__bfloat16_as_ushort(h0) | ((uint32_t)__bfloat16_as_ushort(h1) << 16);
            hp.y = (uint32_t)__bfloat16_as_ushort(h2) | ((uint32_t)__bfloat16_as_ushort(h3) << 16);
            lp.x = (uint32_t)__bfloat16_as_ushort(l0) | ((uint32_t)__bfloat16_as_ushort(l1) << 16);
            lp.y = (uint32_t)__bfloat16_as_ushort(l2) | ((uint32_t)__bfloat16_as_ushort(l3) << 16);
            uint32_t off = (uint32_t)(r * XS + c4 * 4) * 2;
            *(uint2*)(sXh + off) = hp;
            *(uint2*)(sXl + off) = lp;
        }
        __syncthreads();

        // ---- compute: warp grid 2x4, warp tile 32 rows x 32 cols ----
        float c[2][4][4];
        #pragma unroll
        for (int mt = 0; mt < 2; mt++)
            #pragma unroll
            for (int nt = 0; nt < 4; nt++)
                #pragma unroll
                for (int j = 0; j < 4; j++) c[mt][nt][j] = 0.f;

        #pragma unroll
        for (int ks = 0; ks < 8; ks++) {
            uint32_t ah[2][4], al[2][4];
            #pragma unroll
            for (int mt = 0; mt < 2; mt++) {
                uint32_t aoff = (uint32_t)((mrow + mt * 16 + a_row) * XS + ks * 16 + a_kq * 8) * 2;
                LDSM_X4(ah[mt][0], ah[mt][1], ah[mt][2], ah[mt][3], sXh_b + aoff);
                LDSM_X4(al[mt][0], al[mt][1], al[mt][2], al[mt][3], sXl_b + aoff);
            }
            uint32_t bh[4][2], bl[4][2];
            #pragma unroll
            for (int np = 0; np < 2; np++) {
                uint32_t boff = (uint32_t)((ncol + np * 16 + b_nrow) * XS + ks * 16 + b_kq * 8) * 2;
                LDSM_X4(bh[np*2][0], bh[np*2][1], bh[np*2+1][0], bh[np*2+1][1], sWh_b + boff);
                LDSM_X4(bl[np*2][0], bl[np*2][1], bl[np*2+1][0], bl[np*2+1][1], sWl_b + boff);
            }
            #pragma unroll
            for (int nt = 0; nt < 4; nt++) {
                #pragma unroll
                for (int mt = 0; mt < 2; mt++) {
                    MMA_BF16(c[mt][nt], ah[mt], bh[nt]);
                    MMA_BF16(c[mt][nt], ah[mt], bl[nt]);
                    MMA_BF16(c[mt][nt], al[mt], bh[nt]);
                }
            }
        }

        // ---- epilogue: fragments -> smem (overlay on X tiles) -> coalesced ----
        __syncthreads();                       // all LDSM reads of sX done
        #pragma unroll
        for (int mt = 0; mt < 2; mt++) {
            int r = mrow + mt * 16 + qrow;
            #pragma unroll
            for (int nt = 0; nt < 4; nt++) {
                int n = ncol + nt * 8 + qcol;
                *(float2*)&sC[r * CS + n]       = make_float2(c[mt][nt][0], c[mt][nt][1]);
                *(float2*)&sC[(r + 8) * CS + n] = make_float2(c[mt][nt][2], c[mt][nt][3]);
            }
        }
        __syncthreads();
        #pragma unroll
        for (int i = 0; i < 8; i++) {
            int idx = tid + i * 256;           // 2048 float4 = 64 r x 32 c4
            int r = idx >> 5, c4 = idx & 31;
            int gr = row0 + r;
            if (gr < NN) {
                float4 v = *(float4*)&sC[r * CS + c4 * 4];
                *(float4*)&h[(size_t)gr * 128 + c4 * 4] = v;
            }
        }
        __syncthreads();                       // sC reads done before next X stage
    }
}

// ---------------- aggregation (atomic-free CSR gather) ----------------
__global__ __launch_bounds__(256) void agg_kernel(const float* __restrict__ h,
                                                  const float* __restrict__ bias,
                                                  float* __restrict__ out) {
    int n = (blockIdx.x * blockDim.x + threadIdx.x) >> 5;
    if (n >= NN) return;
    int lane = threadIdx.x & 31;
    int c0   = lane * 4;

    float dn = g_dinv[n];
    float4 hn = *(const float4*)&h[(size_t)n * 128 + c0];
    float sw = dn * dn;
    float4 a = make_float4(hn.x * sw, hn.y * sw, hn.z * sw, hn.w * sw);

    int e  = g_rs[n];
    int s1 = g_rs[n + 1];
    for (; e + 4 <= s1; e += 4) {
        int i0 = g_csrc[e], i1 = g_csrc[e + 1], i2 = g_csrc[e + 2], i3 = g_csrc[e + 3];
        float w0 = g_dinv[i0] * dn, w1 = g_dinv[i1] * dn;
        float w2 = g_dinv[i2] * dn, w3 = g_dinv[i3] * dn;
        float4 h0 = *(const float4*)&h[(size_t)i0 * 128 + c0];
        float4 h1 = *(const float4*)&h[(size_t)i1 * 128 + c0];
        float4 h2 = *(const float4*)&h[(size_t)i2 * 128 + c0];
        float4 h3 = *(const float4*)&h[(size_t)i3 * 128 + c0];
        a.x += h0.x * w0 + h1.x * w1 + h2.x * w2 + h3.x * w3;
        a.y += h0.y * w0 + h1.y * w1 + h2.y * w2 + h3.y * w3;
        a.z += h0.z * w0 + h1.z * w1 + h2.z * w2 + h3.z * w3;
        a.w += h0.w * w0 + h1.w * w1 + h2.w * w2 + h3.w * w3;
    }
    for (; e < s1; ++e) {
        int s = g_csrc[e];
        float w = g_dinv[s] * dn;
        float4 hv = *(const float4*)&h[(size_t)s * 128 + c0];
        a.x += hv.x * w; a.y += hv.y * w; a.z += hv.z * w; a.w += hv.w * w;
    }
    float4 bv = *(const float4*)&bias[c0];
    a.x = fmaxf(a.x + bv.x, 0.f);
    a.y = fmaxf(a.y + bv.y, 0.f);
    a.z = fmaxf(a.z + bv.z, 0.f);
    a.w = fmaxf(a.w + bv.w, 0.f);
    *(float4*)&out[(size_t)n * 128 + c0] = a;
}

// ---------------- launch ----------------
extern "C" void kernel_launch(void* const* d_in, const int* in_sizes, int n_in,
                              void* d_out, int out_size) {
    const int*   ei  = (const int*)d_in[0];      // [2, 600000]
    const float* emb = (const float*)d_in[1];    // [100000, 128]
    const float* Ws  = (const float*)d_in[2];    // [3, 128, 128]
    const float* bs  = (const float*)d_in[3];    // [3, 128]
    float* out = (float*)d_out;

    const int* src = ei;
    const int* dst = ei + EE;

    float *ph, *px1, *px2;
    cudaGetSymbolAddress((void**)&ph,  g_h);
    cudaGetSymbolAddress((void**)&px1, g_x1);
    cudaGetSymbolAddress((void**)&px2, g_x2);

    static cudaStream_t s1 = nullptr, s2 = nullptr;
    static cudaEvent_t  e0, e1, e2;
    if (!s1) {
        cudaStreamCreateWithFlags(&s1, cudaStreamNonBlocking);
        cudaStreamCreateWithFlags(&s2, cudaStreamNonBlocking);
        cudaEventCreateWithFlags(&e0, cudaEventDisableTiming);
        cudaEventCreateWithFlags(&e1, cudaEventDisableTiming);
        cudaEventCreateWithFlags(&e2, cudaEventDisableTiming);
        cudaFuncSetAttribute(gemm_tc_kernel, cudaFuncAttributeMaxDynamicSharedMemorySize, SM_TOTAL_G);
    }

    const int TB = 256;
    int gN = (NN + TB - 1) / TB;
    int gE = (EE + TB - 1) / TB;
    int gA = (NN * 32 + TB - 1) / TB;   // one warp per node

    // ---- fork: preproc (s1)  ||  prep_w + gemm0 (s2) ----
    cudaEventRecord(e0, 0);
    cudaStreamWaitEvent(s1, e0, 0);
    cudaStreamWaitEvent(s2, e0, 0);

    init_kernel  <<<gN, TB, 0, s1>>>();
    count_kernel <<<gE, TB, 0, s1>>>(dst);
    dinv_kernel  <<<gN, TB, 0, s1>>>();
    scan1_kernel <<<SCAN_NB, 1024, 0, s1>>>();
    scan2_kernel <<<1, 32, 0, s1>>>();
    scan3_kernel <<<SCAN_NB, 1024, 0, s1>>>();
    fill_kernel  <<<gE, TB, 0, s1>>>(src, dst);

    prep_w_kernel <<<(3 * 16384 + 255) / 256, 256, 0, s2>>>(Ws);
    gemm_tc_kernel<<<GPER, 256, SM_TOTAL_G, s2>>>(emb, 0, ph);

    cudaEventRecord(e1, s1);
    cudaEventRecord(e2, s2);
    cudaStreamWaitEvent(0, e1, 0);
    cudaStreamWaitEvent(0, e2, 0);

    // ---- join: serial dependency chain on default stream ----
    agg_kernel    <<<gA, TB>>>(ph, bs,       px1);
    gemm_tc_kernel<<<GPER, 256, SM_TOTAL_G>>>(px1, 1, ph);
    agg_kernel    <<<gA, TB>>>(ph, bs + 128, px2);
    gemm_tc_kernel<<<GPER, 256, SM_TOTAL_G>>>(px2, 2, ph);
    agg_kernel    <<<gA, TB>>>(ph, bs + 256, out);
}

// round 10
// speedup vs baseline: 1.2209x; 1.0797x over previous
#include <cuda_runtime.h>
#include <cuda_bf16.h>
#include <cstdint>

#define NN 100000
#define EE 600000
#define SCAN_NB 98   // 98 * 1024 >= 100000

// ---------------- scratch (device globals; no allocs allowed) ----------------
__device__ float g_h [(size_t)NN * 128];
__device__ float g_x1[(size_t)NN * 128];
__device__ float g_x2[(size_t)NN * 128];
__device__ float g_dinv[NN];
__device__ int   g_deg[NN];
__device__ int   g_cur[NN];
__device__ int   g_rs[NN + 1];
__device__ int   g_csrc[EE];
__device__ int   g_bsum[SCAN_NB];
__device__ int   g_boff[SCAN_NB];
// pre-split W, transposed: Bt[n][k] = W[k][n], bf16 hi/lo, 3 layers
__device__ __align__(16) __nv_bfloat16 g_Bhi[3 * 128 * 128];
__device__ __align__(16) __nv_bfloat16 g_Blo[3 * 128 * 128];

// ---------------- PTX helpers (plain sm_103-safe: ldmatrix + mma.sync) -------
__device__ __forceinline__ uint32_t smem_u32(const void* p) {
    uint32_t a;
    asm("{ .reg .u64 t; cvta.to.shared.u64 t, %1; cvt.u32.u64 %0, t; }" : "=r"(a) : "l"(p));
    return a;
}
#define LDSM_X4(r0, r1, r2, r3, addr) \
    asm volatile("ldmatrix.sync.aligned.m8n8.x4.shared.b16 {%0,%1,%2,%3}, [%4];" \
                 : "=r"(r0), "=r"(r1), "=r"(r2), "=r"(r3) : "r"(addr))
#define MMA_BF16(c, a, b) \
    asm volatile("mma.sync.aligned.m16n8k16.row.col.f32.bf16.bf16.f32 " \
                 "{%0,%1,%2,%3}, {%4,%5,%6,%7}, {%8,%9}, {%0,%1,%2,%3};" \
                 : "+f"((c)[0]), "+f"((c)[1]), "+f"((c)[2]), "+f"((c)[3]) \
                 : "r"((a)[0]), "r"((a)[1]), "r"((a)[2]), "r"((a)[3]), \
                   "r"((b)[0]), "r"((b)[1]))

// ---------------- graph preprocessing ----------------
__global__ void init_kernel() {
    int i = blockIdx.x * blockDim.x + threadIdx.x;
    if (i < NN) { g_deg[i] = 0; g_cur[i] = 0; }
}
__global__ void count_kernel(const int* __restrict__ dst) {
    int e = blockIdx.x * blockDim.x + threadIdx.x;
    if (e < EE) atomicAdd(&g_deg[dst[e]], 1);
}
__global__ void dinv_kernel() {
    int i = blockIdx.x * blockDim.x + threadIdx.x;
    if (i < NN) g_dinv[i] = rsqrtf((float)(g_deg[i] + 1));
}
__global__ void scan1_kernel() {
    __shared__ int ws[32];
    int tid = threadIdx.x, lane = tid & 31, w = tid >> 5;
    int i = blockIdx.x * 1024 + tid;
    int v = (i < NN) ? g_deg[i] : 0;
    int x = v;
    #pragma unroll
    for (int o = 1; o < 32; o <<= 1) {
        int y = __shfl_up_sync(0xffffffffu, x, o);
        if (lane >= o) x += y;
    }
    if (lane == 31) ws[w] = x;
    __syncthreads();
    if (w == 0) {
        int s = ws[lane];
        #pragma unroll
        for (int o = 1; o < 32; o <<= 1) {
            int y = __shfl_up_sync(0xffffffffu, s, o);
            if (lane >= o) s += y;
        }
        ws[lane] = s;
    }
    __syncthreads();
    int off = (w == 0) ? 0 : ws[w - 1];
    if (i < NN) g_rs[i] = off + x - v;
    if (tid == 0) g_bsum[blockIdx.x] = ws[31];
}
__global__ void scan2_kernel() {
    if (threadIdx.x == 0) {
        int run = 0;
        for (int i = 0; i < SCAN_NB; i++) { int t = g_bsum[i]; g_boff[i] = run; run += t; }
        g_rs[NN] = run;
    }
}
__global__ void scan3_kernel() {
    int i = blockIdx.x * 1024 + threadIdx.x;
    if (i < NN) g_rs[i] += g_boff[blockIdx.x];
}
__global__ void fill_kernel(const int* __restrict__ src, const int* __restrict__ dst) {
    int e = blockIdx.x * blockDim.x + threadIdx.x;
    if (e < EE) {
        int d = dst[e];
        int p = atomicAdd(&g_cur[d], 1);
        g_csrc[g_rs[d] + p] = src[e];
    }
}

// ---------------- W prep: Bt[n][k] = W[k][n], split fp32 -> bf16 hi/lo -------
__global__ void prep_w_kernel(const float* __restrict__ Ws) {
    int idx = blockIdx.x * blockDim.x + threadIdx.x;
    if (idx >= 3 * 16384) return;
    int l = idx >> 14, rem = idx & 16383;
    int n = rem >> 7, k = rem & 127;
    float v = Ws[l * 16384 + k * 128 + n];
    __nv_bfloat16 hi = __float2bfloat16(v);
    __nv_bfloat16 lo = __float2bfloat16(v - __bfloat162float(hi));
    g_Bhi[l * 16384 + n * 128 + k] = hi;
    g_Blo[l * 16384 + n * 128 + k] = lo;
}

// ---------------- persistent tensor-core GEMM (bf16 2-term split) ------------
// h[N,128] = x[N,128] @ W[128,128]; D = xh*wh + xh*wl + xl*wh, fp32 accum.
// Persistent 296 CTAs (2/SM); W staged once; X loads software-pipelined in regs;
// direct fragment->global epilogue (2 barriers/iter).
#define XS 136
#define XT_B (64  * XS * 2)   // 17408 per X tile
#define WT_B (128 * XS * 2)   // 34816 per W tile
#define SM_TOTAL_G (2 * XT_B + 2 * WT_B)   // 104448
#define GPER 296               // persistent grid (2 x 148 SMs)
#define NTILES ((NN + 63) / 64)

__global__ __launch_bounds__(256, 2) void gemm_tc_kernel(const float* __restrict__ x,
                                                         int layer,
                                                         float* __restrict__ h) {
    extern __shared__ __align__(16) char smem[];
    char* sXh = smem;
    char* sXl = smem + XT_B;
    char* sWh = smem + 2 * XT_B;
    char* sWl = smem + 2 * XT_B + WT_B;

    int tid = threadIdx.x, lane = tid & 31, wid = tid >> 5;

    // ---- stage W tiles once (pre-split bf16, L2-resident) ----
    {
        const uint4* bh = (const uint4*)(g_Bhi + layer * 16384);
        const uint4* bl = (const uint4*)(g_Blo + layer * 16384);
        #pragma unroll
        for (int i = 0; i < 8; i++) {
            int idx = tid + i * 256;            // 2048 uint4 = 128 n x 16 kq
            int n = idx >> 4, kq = idx & 15;
            uint32_t off = (uint32_t)(n * XS + kq * 8) * 2;
            *(uint4*)(sWh + off) = bh[idx];
            *(uint4*)(sWl + off) = bl[idx];
        }
    }

    int mrow = (wid >> 2) * 32;     // 0 / 32
    int ncol = (wid & 3) * 32;      // 0 / 32 / 64 / 96
    uint32_t sXh_b = smem_u32(sXh), sXl_b = smem_u32(sXl);
    uint32_t sWh_b = smem_u32(sWh), sWl_b = smem_u32(sWl);
    int a_row = lane & 15, a_kq = lane >> 4;
    int b_nrow = ((lane >> 4) & 1) * 8 + (lane & 7);
    int b_kq   = (lane >> 3) & 1;
    int qrow = lane >> 2;
    int qcol = (lane & 3) * 2;
    int s_r  = tid >> 5, s_c4 = tid & 31;    // staging row/col4 (i-th chunk adds 8 rows)

    // ---- prologue: load first tile into registers ----
    float4 v[8];
    if (blockIdx.x < NTILES) {
        #pragma unroll
        for (int i = 0; i < 8; i++) {
            int gr = blockIdx.x * 64 + s_r + i * 8;
            v[i] = (gr < NN) ? *(const float4*)&x[(size_t)gr * 128 + s_c4 * 4]
                             : make_float4(0.f, 0.f, 0.f, 0.f);
        }
    }

    for (int tile = blockIdx.x; tile < NTILES; tile += GPER) {
        int row0 = tile * 64;

        // ---- convert prefetched regs -> bf16 hi/lo smem ----
        #pragma unroll
        for (int i = 0; i < 8; i++) {
            float4 w4 = v[i];
            __nv_bfloat162 hA = __floats2bfloat162_rn(w4.x, w4.y);
            __nv_bfloat162 hB = __floats2bfloat162_rn(w4.z, w4.w);
            float lx = w4.x - __low2float(hA),  ly = w4.y - __high2float(hA);
            float lz = w4.z - __low2float(hB),  lw = w4.w - __high2float(hB);
            __nv_bfloat162 lA = __floats2bfloat162_rn(lx, ly);
            __nv_bfloat162 lB = __floats2bfloat162_rn(lz, lw);
            uint2 hp, lp;
            hp.x = *(uint32_t*)&hA; hp.y = *(uint32_t*)&hB;
            lp.x = *(uint32_t*)&lA; lp.y = *(uint32_t*)&lB;
            uint32_t off = (uint32_t)((s_r + i * 8) * XS + s_c4 * 4) * 2;
            *(uint2*)(sXh + off) = hp;
            *(uint2*)(sXl + off) = lp;
        }
        __syncthreads();

        // ---- prefetch next tile into registers (lands under compute) ----
        int ntile = tile + GPER;
        if (ntile < NTILES) {
            #pragma unroll
            for (int i = 0; i < 8; i++) {
                int gr = ntile * 64 + s_r + i * 8;
                v[i] = (gr < NN) ? *(const float4*)&x[(size_t)gr * 128 + s_c4 * 4]
                                 : make_float4(0.f, 0.f, 0.f, 0.f);
            }
        }

        // ---- compute: warp grid 2x4, warp tile 32 rows x 32 cols ----
        float c[2][4][4];
        #pragma unroll
        for (int mt = 0; mt < 2; mt++)
            #pragma unroll
            for (int nt = 0; nt < 4; nt++)
                #pragma unroll
                for (int j = 0; j < 4; j++) c[mt][nt][j] = 0.f;

        #pragma unroll
        for (int ks = 0; ks < 8; ks++) {
            uint32_t ah[2][4], al[2][4];
            #pragma unroll
            for (int mt = 0; mt < 2; mt++) {
                uint32_t aoff = (uint32_t)((mrow + mt * 16 + a_row) * XS + ks * 16 + a_kq * 8) * 2;
                LDSM_X4(ah[mt][0], ah[mt][1], ah[mt][2], ah[mt][3], sXh_b + aoff);
                LDSM_X4(al[mt][0], al[mt][1], al[mt][2], al[mt][3], sXl_b + aoff);
            }
            uint32_t bh[4][2], bl[4][2];
            #pragma unroll
            for (int np = 0; np < 2; np++) {
                uint32_t boff = (uint32_t)((ncol + np * 16 + b_nrow) * XS + ks * 16 + b_kq * 8) * 2;
                LDSM_X4(bh[np*2][0], bh[np*2][1], bh[np*2+1][0], bh[np*2+1][1], sWh_b + boff);
                LDSM_X4(bl[np*2][0], bl[np*2][1], bl[np*2+1][0], bl[np*2+1][1], sWl_b + boff);
            }
            #pragma unroll
            for (int nt = 0; nt < 4; nt++) {
                #pragma unroll
                for (int mt = 0; mt < 2; mt++) {
                    MMA_BF16(c[mt][nt], ah[mt], bh[nt]);
                    MMA_BF16(c[mt][nt], ah[mt], bl[nt]);
                    MMA_BF16(c[mt][nt], al[mt], bh[nt]);
                }
            }
        }

        // ---- epilogue: direct fragment -> global (sectors coalesce in L2) ----
        #pragma unroll
        for (int mt = 0; mt < 2; mt++) {
            int r_lo = row0 + mrow + mt * 16 + qrow;
            int r_hi = r_lo + 8;
            #pragma unroll
            for (int nt = 0; nt < 4; nt++) {
                int n = ncol + nt * 8 + qcol;
                if (r_lo < NN) *(float2*)&h[(size_t)r_lo * 128 + n] = make_float2(c[mt][nt][0], c[mt][nt][1]);
                if (r_hi < NN) *(float2*)&h[(size_t)r_hi * 128 + n] = make_float2(c[mt][nt][2], c[mt][nt][3]);
            }
        }
        __syncthreads();   // sX reads done before next iter's convert overwrites
    }
}

// ---------------- aggregation (atomic-free CSR gather) ----------------
__global__ __launch_bounds__(256) void agg_kernel(const float* __restrict__ h,
                                                  const float* __restrict__ bias,
                                                  float* __restrict__ out) {
    int n = (blockIdx.x * blockDim.x + threadIdx.x) >> 5;
    if (n >= NN) return;
    int lane = threadIdx.x & 31;
    int c0   = lane * 4;

    float dn = g_dinv[n];
    float4 hn = *(const float4*)&h[(size_t)n * 128 + c0];
    float sw = dn * dn;
    float4 a = make_float4(hn.x * sw, hn.y * sw, hn.z * sw, hn.w * sw);

    int e  = g_rs[n];
    int s1 = g_rs[n + 1];
    for (; e + 4 <= s1; e += 4) {
        int i0 = g_csrc[e], i1 = g_csrc[e + 1], i2 = g_csrc[e + 2], i3 = g_csrc[e + 3];
        float w0 = g_dinv[i0] * dn, w1 = g_dinv[i1] * dn;
        float w2 = g_dinv[i2] * dn, w3 = g_dinv[i3] * dn;
        float4 h0 = *(const float4*)&h[(size_t)i0 * 128 + c0];
        float4 h1 = *(const float4*)&h[(size_t)i1 * 128 + c0];
        float4 h2 = *(const float4*)&h[(size_t)i2 * 128 + c0];
        float4 h3 = *(const float4*)&h[(size_t)i3 * 128 + c0];
        a.x += h0.x * w0 + h1.x * w1 + h2.x * w2 + h3.x * w3;
        a.y += h0.y * w0 + h1.y * w1 + h2.y * w2 + h3.y * w3;
        a.z += h0.z * w0 + h1.z * w1 + h2.z * w2 + h3.z * w3;
        a.w += h0.w * w0 + h1.w * w1 + h2.w * w2 + h3.w * w3;
    }
    for (; e < s1; ++e) {
        int s = g_csrc[e];
        float w = g_dinv[s] * dn;
        float4 hv = *(const float4*)&h[(size_t)s * 128 + c0];
        a.x += hv.x * w; a.y += hv.y * w; a.z += hv.z * w; a.w += hv.w * w;
    }
    float4 bv = *(const float4*)&bias[c0];
    a.x = fmaxf(a.x + bv.x, 0.f);
    a.y = fmaxf(a.y + bv.y, 0.f);
    a.z = fmaxf(a.z + bv.z, 0.f);
    a.w = fmaxf(a.w + bv.w, 0.f);
    *(float4*)&out[(size_t)n * 128 + c0] = a;
}

// ---------------- launch ----------------
extern "C" void kernel_launch(void* const* d_in, const int* in_sizes, int n_in,
                              void* d_out, int out_size) {
    const int*   ei  = (const int*)d_in[0];      // [2, 600000]
    const float* emb = (const float*)d_in[1];    // [100000, 128]
    const float* Ws  = (const float*)d_in[2];    // [3, 128, 128]
    const float* bs  = (const float*)d_in[3];    // [3, 128]
    float* out = (float*)d_out;

    const int* src = ei;
    const int* dst = ei + EE;

    float *ph, *px1, *px2;
    cudaGetSymbolAddress((void**)&ph,  g_h);
    cudaGetSymbolAddress((void**)&px1, g_x1);
    cudaGetSymbolAddress((void**)&px2, g_x2);

    static cudaStream_t s1 = nullptr, s2 = nullptr;
    static cudaEvent_t  e0, e1, e2;
    if (!s1) {
        cudaStreamCreateWithFlags(&s1, cudaStreamNonBlocking);
        cudaStreamCreateWithFlags(&s2, cudaStreamNonBlocking);
        cudaEventCreateWithFlags(&e0, cudaEventDisableTiming);
        cudaEventCreateWithFlags(&e1, cudaEventDisableTiming);
        cudaEventCreateWithFlags(&e2, cudaEventDisableTiming);
        cudaFuncSetAttribute(gemm_tc_kernel, cudaFuncAttributeMaxDynamicSharedMemorySize, SM_TOTAL_G);
    }

    const int TB = 256;
    int gN = (NN + TB - 1) / TB;
    int gE = (EE + TB - 1) / TB;
    int gA = (NN * 32 + TB - 1) / TB;   // one warp per node

    // ---- fork: preproc (s1)  ||  prep_w + gemm0 (s2) ----
    cudaEventRecord(e0, 0);
    cudaStreamWaitEvent(s1, e0, 0);
    cudaStreamWaitEvent(s2, e0, 0);

    init_kernel  <<<gN, TB, 0, s1>>>();
    count_kernel <<<gE, TB, 0, s1>>>(dst);
    dinv_kernel  <<<gN, TB, 0, s1>>>();
    scan1_kernel <<<SCAN_NB, 1024, 0, s1>>>();
    scan2_kernel <<<1, 32, 0, s1>>>();
    scan3_kernel <<<SCAN_NB, 1024, 0, s1>>>();
    fill_kernel  <<<gE, TB, 0, s1>>>(src, dst);

    prep_w_kernel <<<(3 * 16384 + 255) / 256, 256, 0, s2>>>(Ws);
    gemm_tc_kernel<<<GPER, 256, SM_TOTAL_G, s2>>>(emb, 0, ph);

    cudaEventRecord(e1, s1);
    cudaEventRecord(e2, s2);
    cudaStreamWaitEvent(0, e1, 0);
    cudaStreamWaitEvent(0, e2, 0);

    // ---- join: serial dependency chain on default stream ----
    agg_kernel    <<<gA, TB>>>(ph, bs,       px1);
    gemm_tc_kernel<<<GPER, 256, SM_TOTAL_G>>>(px1, 1, ph);
    agg_kernel    <<<gA, TB>>>(ph, bs + 128, px2);
    gemm_tc_kernel<<<GPER, 256, SM_TOTAL_G>>>(px2, 2, ph);
    agg_kernel    <<<gA, TB>>>(ph, bs + 256, out);
}